// round 9
// baseline (speedup 1.0000x reference)
#include <cuda_runtime.h>
#include <cuda_fp16.h>
#include <cstdint>

#define NREL 8
#define F    128
#define NMAX 100000
#define EMAX 1600000
#define NBUCK (NMAX * NREL)

// Scratch (no allocation allowed)
__device__ __align__(16) __half g_Hh[(size_t)NREL * NMAX * F];  // 204.8 MB
__device__ __align__(16) __half g_fh[(size_t)NMAX * F];         // 25.6 MB fp16 feat
__device__ __align__(16) __half g_wh[NREL * F * F];  // transposed: [r][n][k]
// (dst*8+et) counting-sort scratch
__device__ int g_cnt[NBUCK + 1];
__device__ int g_off[NBUCK + 1];
__device__ int g_cur[NBUCK];
__device__ int g_eidx[EMAX];   // src only (relation implied by segment)
__device__ int g_bsum[1024];

// ---------------------------------------------------------------------------
// Fused setup: feat fp32->fp16, weight [r][k][n] -> fp16 transposed [r][n][k],
// zero the histogram.
// ---------------------------------------------------------------------------
__global__ void setup_kernel(const float* __restrict__ feat,
                             const float* __restrict__ wgt,
                             int n_feat, int n_w, int nb) {
    int i = blockIdx.x * blockDim.x + threadIdx.x;
    if (i < n_feat) g_fh[i] = __float2half_rn(feat[i]);
    if (i < n_w) {
        int r = i >> 14, rem = i & 16383, k = rem >> 7, nn = rem & 127;
        g_wh[r * 16384 + nn * 128 + k] = __float2half_rn(wgt[i]);
    }
    if (i <= nb) g_cnt[i] = 0;
}

// ---------------------------------------------------------------------------
// Counting sort by key = dst*8 + et  (800K buckets, multi-block scan)
// ---------------------------------------------------------------------------
__global__ void hist_kernel(const int* __restrict__ dst,
                            const int* __restrict__ et, int E) {
    int e = blockIdx.x * blockDim.x + threadIdx.x;
    if (e < E) atomicAdd(&g_cnt[dst[e] * NREL + et[e]], 1);
}

// Pass 1: per-block (1024) exclusive scan; block totals -> g_bsum
__global__ void __launch_bounds__(1024) scan1_kernel(int n) {
    const int tid = threadIdx.x, lane = tid & 31, wid = tid >> 5;
    __shared__ int wsum[32];
    int i = blockIdx.x * 1024 + tid;
    int x = (i < n) ? g_cnt[i] : 0;
    int v = x;
#pragma unroll
    for (int d = 1; d < 32; d <<= 1) {
        int t = __shfl_up_sync(0xFFFFFFFFu, v, d);
        if (lane >= d) v += t;
    }
    if (lane == 31) wsum[wid] = v;
    __syncthreads();
    if (wid == 0) {
        int s = wsum[lane];
        int sv = s;
#pragma unroll
        for (int d = 1; d < 32; d <<= 1) {
            int t = __shfl_up_sync(0xFFFFFFFFu, sv, d);
            if (lane >= d) sv += t;
        }
        wsum[lane] = sv - s;  // exclusive warp prefix
    }
    __syncthreads();
    if (i < n) g_off[i] = wsum[wid] + v - x;   // block-local exclusive
    if (tid == 1023) g_bsum[blockIdx.x] = wsum[31] + v;  // block total
}

// Pass 2: single-block exclusive scan of the <=1024 block totals
__global__ void __launch_bounds__(1024) scan2_kernel(int nblk, int n) {
    const int tid = threadIdx.x, lane = tid & 31, wid = tid >> 5;
    __shared__ int wsum[32];
    int x = (tid < nblk) ? g_bsum[tid] : 0;
    int v = x;
#pragma unroll
    for (int d = 1; d < 32; d <<= 1) {
        int t = __shfl_up_sync(0xFFFFFFFFu, v, d);
        if (lane >= d) v += t;
    }
    if (lane == 31) wsum[wid] = v;
    __syncthreads();
    if (wid == 0) {
        int s = wsum[lane];
        int sv = s;
#pragma unroll
        for (int d = 1; d < 32; d <<= 1) {
            int t = __shfl_up_sync(0xFFFFFFFFu, sv, d);
            if (lane >= d) sv += t;
        }
        wsum[lane] = sv - s;
    }
    __syncthreads();
    if (tid < nblk) g_bsum[tid] = wsum[wid] + v - x;
    if (tid == 1023) g_off[n] = wsum[31] + v;   // grand total (= E)
}

// Pass 3: add block offsets; init cursors
__global__ void scan3_kernel(int n) {
    int i = blockIdx.x * blockDim.x + threadIdx.x;
    if (i < n) {
        int o = g_off[i] + g_bsum[i >> 10];
        g_off[i] = o;
        g_cur[i] = o;
    }
}

__global__ void fill_kernel(const int* __restrict__ src,
                            const int* __restrict__ dst,
                            const int* __restrict__ et, int E) {
    int e = blockIdx.x * blockDim.x + threadIdx.x;
    if (e < E) {
        int p = atomicAdd(&g_cur[dst[e] * NREL + et[e]], 1);
        g_eidx[p] = src[e];
    }
}

// ---------------------------------------------------------------------------
// Aggregate fp16 features: one warp per (dst, rel) segment. Gather fp16 rows
// (25.6 MB -> L2-resident, 256 B/row), fp32 accumulate, write fp16 H row.
// ---------------------------------------------------------------------------
__device__ __forceinline__ void acc_h4(float4& acc, uint2 u) {
    __half2 h01 = *reinterpret_cast<__half2*>(&u.x);
    __half2 h23 = *reinterpret_cast<__half2*>(&u.y);
    float2 f01 = __half22float2(h01);
    float2 f23 = __half22float2(h23);
    acc.x += f01.x; acc.y += f01.y; acc.z += f23.x; acc.w += f23.y;
}

__global__ void aggregate_kernel(int n_nodes) {
    int w = (blockIdx.x * blockDim.x + threadIdx.x) >> 5;
    int lane = threadIdx.x & 31;
    if (w >= n_nodes * NREL) return;
    int d = w >> 3, r = w & 7;
    int beg = g_off[w], end = g_off[w + 1];
    float4 acc = make_float4(0.f, 0.f, 0.f, 0.f);
    int j = beg;
    for (; j + 4 <= end; j += 4) {
        int s0 = g_eidx[j], s1 = g_eidx[j + 1];
        int s2 = g_eidx[j + 2], s3 = g_eidx[j + 3];
        uint2 u0 = *reinterpret_cast<const uint2*>(g_fh + (size_t)s0 * F + lane * 4);
        uint2 u1 = *reinterpret_cast<const uint2*>(g_fh + (size_t)s1 * F + lane * 4);
        uint2 u2 = *reinterpret_cast<const uint2*>(g_fh + (size_t)s2 * F + lane * 4);
        uint2 u3 = *reinterpret_cast<const uint2*>(g_fh + (size_t)s3 * F + lane * 4);
        acc_h4(acc, u0); acc_h4(acc, u1); acc_h4(acc, u2); acc_h4(acc, u3);
    }
    for (; j < end; j++) {
        int s = g_eidx[j];
        uint2 u = *reinterpret_cast<const uint2*>(g_fh + (size_t)s * F + lane * 4);
        acc_h4(acc, u);
    }
    __half2 a01 = __halves2half2(__float2half_rn(acc.x), __float2half_rn(acc.y));
    __half2 a23 = __halves2half2(__float2half_rn(acc.z), __float2half_rn(acc.w));
    uint2 uh;
    uh.x = *reinterpret_cast<uint32_t*>(&a01);
    uh.y = *reinterpret_cast<uint32_t*>(&a23);
    *reinterpret_cast<uint2*>(g_Hh + ((size_t)r * n_nodes + d) * F + lane * 4) = uh;
}

// ---------------------------------------------------------------------------
// Legacy-pipe GEMM building blocks
// ---------------------------------------------------------------------------
__device__ __forceinline__ uint32_t smem_u32(const void* p) {
    uint32_t a;
    asm("{ .reg .u64 t; cvta.to.shared.u64 t, %1; cvt.u32.u64 %0, t; }" : "=r"(a) : "l"(p));
    return a;
}

__device__ __forceinline__ void mma16816(float c[4], const uint32_t a[4],
                                         const uint32_t b0, const uint32_t b1) {
    asm volatile(
        "mma.sync.aligned.m16n8k16.row.col.f32.f16.f16.f32 "
        "{%0,%1,%2,%3}, {%4,%5,%6,%7}, {%8,%9}, {%0,%1,%2,%3};"
        : "+f"(c[0]), "+f"(c[1]), "+f"(c[2]), "+f"(c[3])
        : "r"(a[0]), "r"(a[1]), "r"(a[2]), "r"(a[3]), "r"(b0), "r"(b1));
}

#define LDSM_X4(r, addr) \
    asm volatile("ldmatrix.sync.aligned.m8n8.x4.shared.b16 {%0,%1,%2,%3}, [%4];" \
                 : "=r"((r)[0]), "=r"((r)[1]), "=r"((r)[2]), "=r"((r)[3]) : "r"(addr))

#define PITCH_B 272
#define TILE_SZ (128 * PITCH_B)   // 34816 B

__device__ __forceinline__ void cpa_tile(uint32_t s_base, const __half* g,
                                         int valid_rows, int tid) {
    const char* gc = reinterpret_cast<const char*>(g);
#pragma unroll
    for (int it = 0; it < 4; it++) {
        int i = tid + it * 512;
        int m = i >> 4, c = i & 15;
        uint32_t s = s_base + m * PITCH_B + c * 16;
        const char* src = gc + m * 256 + c * 16;
        int sz = (m < valid_rows) ? 16 : 0;
        asm volatile("cp.async.cg.shared.global [%0], [%1], 16, %2;"
                     :: "r"(s), "l"(src), "r"(sz) : "memory");
    }
}

// SMEM map: A x2 buffers, B x2 buffers
#define OFF_A0 0u
#define OFF_A1 34816u
#define OFF_B0 69632u
#define OFF_B1 104448u
#define SMEM_SZ 139264

// ---------------------------------------------------------------------------
// GEMM: per CTA one 128-row dst tile; loop 8 relations with A=H_r, B=W_r;
// ACCUMULATE across relations in registers; write out once.
// ---------------------------------------------------------------------------
__global__ void __launch_bounds__(512, 1) gemm_kernel(float* __restrict__ out,
                                                      int n_nodes) {
    extern __shared__ __align__(128) char smem[];
    const uint32_t sb = smem_u32(smem);
    const int tid = threadIdx.x, wid = tid >> 5, lane = tid & 31;
    const int m0 = blockIdx.x * 128;
    const int valid = n_nodes - m0;

    // Prologue: relation 0 into buffer 0
    cpa_tile(sb + OFF_A0, g_Hh + (size_t)m0 * F, valid, tid);
    cpa_tile(sb + OFF_B0, g_wh, 128, tid);
    asm volatile("cp.async.commit_group;" ::: "memory");

    const int wm = (wid >> 1) * 16;
    const int wn = (wid & 1) * 64;
    const uint32_t a_off =
        (uint32_t)((wm + (lane & 15)) * PITCH_B + ((lane >> 4) * 8) * 2);
    const int b_row = (lane & 7) + ((lane >> 3) & 1) * 8;
    const uint32_t b_koff = (uint32_t)(((lane >> 4) * 8) * 2);

    float acc[8][4];
#pragma unroll
    for (int i = 0; i < 8; i++)
#pragma unroll
        for (int j = 0; j < 4; j++) acc[i][j] = 0.f;

    for (int q = 0; q < NREL; q++) {
        if (q < 7) {  // prefetch next relation into the other buffer
            const int nb1 = (q + 1) & 1;
            cpa_tile(sb + (nb1 ? OFF_A1 : OFF_A0),
                     g_Hh + ((size_t)(q + 1) * n_nodes + m0) * F, valid, tid);
            cpa_tile(sb + (nb1 ? OFF_B1 : OFF_B0),
                     g_wh + (size_t)(q + 1) * F * F, 128, tid);
            asm volatile("cp.async.commit_group;" ::: "memory");
            asm volatile("cp.async.wait_group 1;" ::: "memory");
        } else {
            asm volatile("cp.async.wait_group 0;" ::: "memory");
        }
        __syncthreads();

        const uint32_t ab = sb + ((q & 1) ? OFF_A1 : OFF_A0);
        const uint32_t bb = sb + ((q & 1) ? OFF_B1 : OFF_B0);

#pragma unroll
        for (int kk = 0; kk < 8; kk++) {
            const uint32_t k2 = (uint32_t)(kk * 32);
            uint32_t ah[4];
            LDSM_X4(ah, ab + a_off + k2);
#pragma unroll
            for (int nb = 0; nb < 4; nb++) {
                const uint32_t baddr =
                    bb + (uint32_t)((wn + nb * 16 + b_row) * PITCH_B) + b_koff + k2;
                uint32_t bh[4];
                LDSM_X4(bh, baddr);
                mma16816(acc[nb * 2],     ah, bh[0], bh[2]);
                mma16816(acc[nb * 2 + 1], ah, bh[1], bh[3]);
            }
        }
        __syncthreads();  // all warps done with buf (q&1) before it is refilled
    }

    // Epilogue: single write of the relation-summed tile
    const int r0 = wm + (lane >> 2);
    const bool ok0 = (m0 + r0) < n_nodes;
    const bool ok1 = (m0 + r0 + 8) < n_nodes;
    float* cp = out + (size_t)m0 * F;
#pragma unroll
    for (int ns = 0; ns < 8; ns++) {
        const int col = wn + ns * 8 + (lane & 3) * 2;
        if (ok0) *(float2*)&cp[(size_t)r0 * F + col] =
            make_float2(acc[ns][0], acc[ns][1]);
        if (ok1) *(float2*)&cp[(size_t)(r0 + 8) * F + col] =
            make_float2(acc[ns][2], acc[ns][3]);
    }
}

// ---------------------------------------------------------------------------
extern "C" void kernel_launch(void* const* d_in, const int* in_sizes, int n_in,
                              void* d_out, int out_size) {
    const float* feat   = (const float*)d_in[0];
    const float* weight = (const float*)d_in[1];
    const int*   src    = (const int*)d_in[2];
    const int*   dst    = (const int*)d_in[3];
    const int*   et     = (const int*)d_in[4];

    const int n_nodes = in_sizes[0] / F;
    const int n_feat  = in_sizes[0];
    const int n_w     = in_sizes[1];
    const int E       = in_sizes[2];
    float* out = (float*)d_out;

    const int nb = n_nodes * NREL;            // 800K buckets
    const int nblk = (nb + 1023) / 1024;      // scan blocks (<=1024)

    // Fused setup: feat fp16, W fp16 transposed, zero histogram
    int setup_n = n_feat > (nb + 1) ? n_feat : (nb + 1);
    setup_kernel<<<(setup_n + 255) / 256, 256>>>(feat, weight, n_feat, n_w, nb);

    // Counting sort by (dst, et)
    hist_kernel<<<(E + 255) / 256, 256>>>(dst, et, E);
    scan1_kernel<<<nblk, 1024>>>(nb);
    scan2_kernel<<<1, 1024>>>(nblk, nb);
    scan3_kernel<<<(nb + 255) / 256, 256>>>(nb);
    fill_kernel<<<(E + 255) / 256, 256>>>(src, dst, et, E);

    // Aggregate fp16 features into H[r][d]
    aggregate_kernel<<<(nb * 32 + 255) / 256, 256>>>(n_nodes);

    // Fused relation-sum GEMM: out = sum_r H_r @ W_r
    cudaFuncSetAttribute(gemm_kernel,
                         cudaFuncAttributeMaxDynamicSharedMemorySize, SMEM_SZ);
    gemm_kernel<<<(n_nodes + 127) / 128, 512, SMEM_SZ>>>(out, n_nodes);
}